// round 16
// baseline (speedup 1.0000x reference)
#include <cuda_runtime.h>
#include <cuda_fp16.h>

// ============================================================================
// RFEncoder: 2-layer hetero GATv2 (2 relations, 2 heads, HID=64)
//
// R15: revert R14's relation-split (barrier cost > win). Base = R13 (684us).
// ONE change: layer2 pull processes 2 nodes per warp (16 lanes/node, 8
// comps/lane, 16B fp16 gathers) -> ~1.9x edge throughput per instruction on
// the deduced-dominant kernel. No smem, no block barriers.
// ============================================================================

#define NMAX  100000
#define EMAX  800000
#define EMAXP (EMAX + 4)
#define HD    128   // HEADS * HID

typedef unsigned long long u64;

__device__ __half g_xlh[2][NMAX * HD];
__device__ float  g_xr [2][NMAX * HD];
__device__ float  g_h  [NMAX * 64];
__device__ int    g_rowptr[2][NMAX + 1];
__device__ int    g_cursor[2][NMAX];
__device__ int    g_csrc  [2][EMAXP];

union F4U2 { float4 f; u64 u[2]; };

__device__ __forceinline__ u64 pack2(float lo, float hi) {
    u64 r; asm("mov.b64 %0, {%1, %2};" : "=l"(r) : "f"(lo), "f"(hi)); return r;
}
__device__ __forceinline__ u64 ffma2(u64 a, u64 b, u64 c) {
    u64 d; asm("fma.rn.f32x2 %0, %1, %2, %3;" : "=l"(d) : "l"(a), "l"(b), "l"(c));
    return d;
}

// ---------------------------------------------------------------------------
__global__ void zero2_kernel(int* __restrict__ cur, int n) {
    int i = blockIdx.x * blockDim.x + threadIdx.x;
    if (i < n) { cur[i] = 0; cur[NMAX + i] = 0; }
}

__global__ void hist2_kernel(const int* __restrict__ dst0,
                             const int* __restrict__ dst1,
                             int* __restrict__ cur, int E) {
    int e = blockIdx.x * blockDim.x + threadIdx.x;
    if (e >= E) return;
    const int* d = blockIdx.y ? dst1 : dst0;
    atomicAdd(&cur[blockIdx.y * NMAX + d[e]], 1);
}

__global__ void scan2_kernel(int* __restrict__ cursor, int* __restrict__ rowptr,
                             int n) {
    __shared__ int part[1024];
    int r = blockIdx.x;
    int* cur = cursor + r * NMAX;
    int* rp  = rowptr + r * (NMAX + 1);
    int t = threadIdx.x;
    int chunk = (n + 1023) / 1024;
    int lo = t * chunk;
    int hi = lo + chunk; if (hi > n) hi = n;

    int s = 0;
    for (int i = lo; i < hi; i++) s += cur[i];
    part[t] = s;
    __syncthreads();
    for (int d = 1; d < 1024; d <<= 1) {
        int v = (t >= d) ? part[t - d] : 0;
        __syncthreads();
        part[t] += v;
        __syncthreads();
    }
    int off = (t == 0) ? 0 : part[t - 1];
    for (int i = lo; i < hi; i++) {
        int dv = cur[i];
        rp[i] = off;
        cur[i] = off;
        off += dv;
    }
    if (hi == n) rp[n] = off;
}

__global__ void scatter2_kernel(const int* __restrict__ ea,
                                const int* __restrict__ er,
                                int* __restrict__ cursor,
                                int* __restrict__ csrc, int E) {
    int e = blockIdx.x * blockDim.x + threadIdx.x;
    if (e >= E) return;
    int r = blockIdx.y;
    const int* edges = r ? er : ea;
    int pos = atomicAdd(&cursor[r * NMAX + edges[E + e]], 1);
    csrc[r * EMAXP + pos] = edges[e];
}

// ---------------------------------------------------------------------------
// Layer 1, fully fused (R13 version, unchanged: 123.5us measured).
__global__ void __launch_bounds__(128, 8)
layer1_fused_kernel(const int* __restrict__ rowptr,
                    const int* __restrict__ csrc,
                    const float* __restrict__ x,
                    const float* __restrict__ Wl,
                    const float* __restrict__ bl,
                    const float* __restrict__ Wr,
                    const float* __restrict__ br,
                    const float* __restrict__ att,
                    const float* __restrict__ bias,
                    float* __restrict__ h, int n) {
    const unsigned F = 0xffffffffu;
    int node = (blockIdx.x * blockDim.x + threadIdx.x) >> 5;
    if (node >= n) return;
    int lane = threadIdx.x & 31;
    int r4   = lane & 3;

    const float2 xd = ((const float2*)x)[node];
    float4 outv = make_float4(0.f, 0.f, 0.f, 0.f);

#pragma unroll 1
    for (int r = 0; r < 2; r++) {
        const float4 wl0 = *(const float4*)&Wl[r * 256 + lane * 4];
        const float4 wl1 = *(const float4*)&Wl[r * 256 + HD + lane * 4];
        const float4 blv = *(const float4*)&bl[r * HD + lane * 4];
        const float4 a4  = *(const float4*)&att[r * HD + lane * 4];

        float4 base;
        {
            const float4 wr0 = *(const float4*)&Wr[r * 256 + lane * 4];
            const float4 wr1 = *(const float4*)&Wr[r * 256 + HD + lane * 4];
            const float4 brv = *(const float4*)&br[r * HD + lane * 4];
            base.x = fmaf(xd.y, wr1.x, fmaf(xd.x, wr0.x, brv.x)) + blv.x;
            base.y = fmaf(xd.y, wr1.y, fmaf(xd.x, wr0.y, brv.y)) + blv.y;
            base.z = fmaf(xd.y, wr1.z, fmaf(xd.x, wr0.z, brv.z)) + blv.z;
            base.w = fmaf(xd.y, wr1.w, fmaf(xd.x, wr0.w, brv.w)) + blv.w;
        }

        const int* rp = rowptr + r * (NMAX + 1);
        const int* cs = csrc   + r * EMAXP;
        int beg = rp[node];
        int end = rp[node + 1];

        float S0 = 0.f, S1 = 0.f, den = 0.f;

        for (int j = beg & ~3; j < end; j += 4) {
            int4 s4 = *(const int4*)&cs[j];

            float2 q0 = ((const float2*)x)[s4.x];
            float2 q1 = ((const float2*)x)[s4.y];
            float2 q2 = ((const float2*)x)[s4.z];
            float2 q3 = ((const float2*)x)[s4.w];

            float sc0, sc1, sc2, sc3;
#define SCORE1(sc, q) { \
    float v0 = fmaf(q.y, wl1.x, fmaf(q.x, wl0.x, base.x)); \
    float v1 = fmaf(q.y, wl1.y, fmaf(q.x, wl0.y, base.y)); \
    float v2 = fmaf(q.y, wl1.z, fmaf(q.x, wl0.z, base.z)); \
    float v3 = fmaf(q.y, wl1.w, fmaf(q.x, wl0.w, base.w)); \
    v0 = v0 > 0.f ? v0 : 0.2f * v0; \
    v1 = v1 > 0.f ? v1 : 0.2f * v1; \
    v2 = v2 > 0.f ? v2 : 0.2f * v2; \
    v3 = v3 > 0.f ? v3 : 0.2f * v3; \
    float pA = v0 * a4.x; \
    float pB = v1 * a4.y; \
    pA = fmaf(v2, a4.z, pA); \
    pB = fmaf(v3, a4.w, pB); \
    sc = pA + pB; }
            SCORE1(sc0, q0) SCORE1(sc1, q1) SCORE1(sc2, q2) SCORE1(sc3, q3)
#undef SCORE1

#pragma unroll
            for (int d = 2; d >= 1; d >>= 1) {
                sc0 += __shfl_xor_sync(F, sc0, d);
                sc1 += __shfl_xor_sync(F, sc1, d);
                sc2 += __shfl_xor_sync(F, sc2, d);
                sc3 += __shfl_xor_sync(F, sc3, d);
            }
            float v = (r4 < 2) ? (r4 ? sc1 : sc0) : ((r4 == 2) ? sc2 : sc3);
            v += __shfl_xor_sync(F, v, 4);
            v += __shfl_xor_sync(F, v, 8);

            int idx = j + r4;
            float ev = (idx >= beg && idx < end) ? __expf(v) : 0.f;

            float qx = (r4 < 2) ? (r4 ? q1.x : q0.x) : ((r4 == 2) ? q2.x : q3.x);
            float qy = (r4 < 2) ? (r4 ? q1.y : q0.y) : ((r4 == 2) ? q2.y : q3.y);
            S0 = fmaf(ev, qx, S0);
            S1 = fmaf(ev, qy, S1);
            den += ev;
        }

        S0  += __shfl_xor_sync(F, S0, 2);  S0  += __shfl_xor_sync(F, S0, 1);
        S1  += __shfl_xor_sync(F, S1, 2);  S1  += __shfl_xor_sync(F, S1, 1);
        den += __shfl_xor_sync(F, den, 2); den += __shfl_xor_sync(F, den, 1);

        float inv = 0.25f / (den + 1e-16f);
        outv.x = fmaf(fmaf(S1, wl1.x, fmaf(S0, wl0.x, den * blv.x)), inv, outv.x);
        outv.y = fmaf(fmaf(S1, wl1.y, fmaf(S0, wl0.y, den * blv.y)), inv, outv.y);
        outv.z = fmaf(fmaf(S1, wl1.z, fmaf(S0, wl0.z, den * blv.z)), inv, outv.z);
        outv.w = fmaf(fmaf(S1, wl1.w, fmaf(S0, wl0.w, den * blv.w)), inv, outv.w);
    }

    outv.x += __shfl_xor_sync(F, outv.x, 16);
    outv.y += __shfl_xor_sync(F, outv.y, 16);
    outv.z += __shfl_xor_sync(F, outv.z, 16);
    outv.w += __shfl_xor_sync(F, outv.w, 16);

    if (lane < 16) {
        int c = lane * 4;
        outv.x += 0.5f * (bias[c + 0] + bias[64 + c + 0]);
        outv.y += 0.5f * (bias[c + 1] + bias[64 + c + 1]);
        outv.z += 0.5f * (bias[c + 2] + bias[64 + c + 2]);
        outv.w += 0.5f * (bias[c + 3] + bias[64 + c + 3]);
        outv.x = outv.x > 0.f ? outv.x : 0.f;
        outv.y = outv.y > 0.f ? outv.y : 0.f;
        outv.z = outv.z > 0.f ? outv.z : 0.f;
        outv.w = outv.w > 0.f ? outv.w : 0.f;
        *(float4*)&h[(size_t)node * 64 + c] = outv;
    }
}

// ---------------------------------------------------------------------------
// Layer-2 transforms with packed f32x2 FMAs (FFMA2) — R13 version, unchanged.
__global__ void __launch_bounds__(128)
transform64_all_kernel(const float* __restrict__ X,
                       const float* __restrict__ Wl,
                       const float* __restrict__ bl,
                       const float* __restrict__ Wr,
                       const float* __restrict__ br,
                       __half* __restrict__ xlh,
                       float* __restrict__ xrf,
                       int n) {
    __shared__ float sW[64 * 128];
    __shared__ float sX[32 * 68];

    int y = blockIdx.y;
    int r = y >> 1;
    bool is_xl = (y & 1) == 0;
    const float* W = is_xl ? (Wl + r * 64 * HD) : (Wr + r * 64 * HD);
    const float* b = is_xl ? (bl + r * HD)      : (br + r * HD);

    int tx = threadIdx.x;
    for (int idx = tx * 4; idx < 64 * 128; idx += 128 * 4)
        *(float4*)&sW[idx] = *(const float4*)&W[idx];

    int node0 = blockIdx.x * 32;
    for (int idx = tx; idx < 512; idx += 128) {
        int rr = idx >> 4;
        int c4 = idx & 15;
        float4 v = make_float4(0.f, 0.f, 0.f, 0.f);
        if (node0 + rr < n)
            v = *(const float4*)&X[(size_t)(node0 + rr) * 64 + c4 * 4];
        *(float4*)&sX[rr * 68 + c4 * 4] = v;
    }
    __syncthreads();

    int cg = tx & 15;
    int ng = tx >> 4;

    u64 acc2[4][4];
    {
        u64 b0 = pack2(b[cg * 8 + 0], b[cg * 8 + 1]);
        u64 b1 = pack2(b[cg * 8 + 2], b[cg * 8 + 3]);
        u64 b2 = pack2(b[cg * 8 + 4], b[cg * 8 + 5]);
        u64 b3 = pack2(b[cg * 8 + 6], b[cg * 8 + 7]);
#pragma unroll
        for (int m = 0; m < 4; m++) {
            acc2[m][0] = b0; acc2[m][1] = b1;
            acc2[m][2] = b2; acc2[m][3] = b3;
        }
    }

    for (int k = 0; k < 64; k += 4) {
        float4 xv[4];
#pragma unroll
        for (int m = 0; m < 4; m++)
            xv[m] = *(const float4*)&sX[(ng * 4 + m) * 68 + k];
#pragma unroll
        for (int kk = 0; kk < 4; kk++) {
            F4U2 w0, w1;
            w0.f = *(const float4*)&sW[(k + kk) * 128 + cg * 8];
            w1.f = *(const float4*)&sW[(k + kk) * 128 + cg * 8 + 4];
#pragma unroll
            for (int m = 0; m < 4; m++) {
                float xs = (kk == 0) ? xv[m].x : (kk == 1) ? xv[m].y
                         : (kk == 2) ? xv[m].z : xv[m].w;
                u64 xs2 = pack2(xs, xs);
                acc2[m][0] = ffma2(xs2, w0.u[0], acc2[m][0]);
                acc2[m][1] = ffma2(xs2, w0.u[1], acc2[m][1]);
                acc2[m][2] = ffma2(xs2, w1.u[0], acc2[m][2]);
                acc2[m][3] = ffma2(xs2, w1.u[1], acc2[m][3]);
            }
        }
    }

    if (is_xl) {
        __half* Y = xlh + (size_t)r * NMAX * HD;
#pragma unroll
        for (int m = 0; m < 4; m++) {
            int node = node0 + ng * 4 + m;
            if (node < n) {
                F4U2 o0, o1;
                o0.u[0] = acc2[m][0]; o0.u[1] = acc2[m][1];
                o1.u[0] = acc2[m][2]; o1.u[1] = acc2[m][3];
                __half2 p0 = __float22half2_rn(make_float2(o0.f.x, o0.f.y));
                __half2 p1 = __float22half2_rn(make_float2(o0.f.z, o0.f.w));
                __half2 p2 = __float22half2_rn(make_float2(o1.f.x, o1.f.y));
                __half2 p3 = __float22half2_rn(make_float2(o1.f.z, o1.f.w));
                uint4 pk;
                pk.x = *(unsigned*)&p0; pk.y = *(unsigned*)&p1;
                pk.z = *(unsigned*)&p2; pk.w = *(unsigned*)&p3;
                *(uint4*)&Y[(size_t)node * HD + cg * 8] = pk;
            }
        }
    } else {
        float* Y = xrf + (size_t)r * NMAX * HD;
#pragma unroll
        for (int m = 0; m < 4; m++) {
            int node = node0 + ng * 4 + m;
            if (node < n) {
                F4U2 o0, o1;
                o0.u[0] = acc2[m][0]; o0.u[1] = acc2[m][1];
                o1.u[0] = acc2[m][2]; o1.u[1] = acc2[m][3];
                *(float4*)&Y[(size_t)node * HD + cg * 8]     = o0.f;
                *(float4*)&Y[(size_t)node * HD + cg * 8 + 4] = o1.f;
            }
        }
    }
}

// ---------------------------------------------------------------------------
// Layer-2 pull: 2 nodes per warp. Half-warp owns a node; lane covers 8 comps
// (16B fp16 gathers). Head0 = hl 0-7, head1 = hl 8-15. Merged reduction
// (strides 2,1 -> select -> stride 4), one __expf/lane, head fold via xor 8.
__global__ void __launch_bounds__(128, 8)
layer2_fused_kernel(const int* __restrict__ rowptr,
                    const int* __restrict__ csrc,
                    const __half* __restrict__ xlh,
                    const float* __restrict__ xrf,
                    const float* __restrict__ att,
                    const float* __restrict__ bias,
                    float* __restrict__ out, int n) {
    const unsigned F = 0xffffffffu;
    int tid  = threadIdx.x;
    int wid  = tid >> 5;
    int lane = tid & 31;
    int hl   = lane & 15;
    int half = lane >> 4;
    int r4   = lane & 3;
    int gbase = lane & ~3;
    int node = blockIdx.x * 8 + wid * 2 + half;
    bool active = node < n;
    int nodec = active ? node : 0;
    int cbase = hl * 8;   // this lane's first component (of 128)

    float4 out0 = make_float4(0.f, 0.f, 0.f, 0.f);
    float4 out1 = make_float4(0.f, 0.f, 0.f, 0.f);

#pragma unroll 1
    for (int r = 0; r < 2; r++) {
        const __half* xl = xlh + (size_t)r * NMAX * HD;
        const float*  xr = xrf + (size_t)r * NMAX * HD;
        const float4 a40 = *(const float4*)&att[r * HD + cbase];
        const float4 a41 = *(const float4*)&att[r * HD + cbase + 4];
        const float4 xv0 = *(const float4*)&xr[(size_t)nodec * HD + cbase];
        const float4 xv1 = *(const float4*)&xr[(size_t)nodec * HD + cbase + 4];

        const int* rp = rowptr + r * (NMAX + 1);
        const int* cs = csrc   + r * EMAXP;
        int beg = rp[nodec];
        int end = active ? rp[nodec + 1] : beg;
        int jb  = beg & ~3;
        int ngr = (end - jb + 3) >> 2;
        int gmax = ngr;
        {
            int o = __shfl_xor_sync(F, gmax, 16);
            gmax = (o > gmax) ? o : gmax;
        }

        float4 ns0 = make_float4(0.f, 0.f, 0.f, 0.f);
        float4 ns1 = make_float4(0.f, 0.f, 0.f, 0.f);
        float den = 0.f;

        for (int it = 0; it < gmax; it++) {
            int j  = jb + it * 4;
            int jh = (j < end) ? j : jb;   // clamp (data masked via ev)
            int4 s4 = *(const int4*)&cs[jh];

            uint4 g0 = *(const uint4*)&xl[(size_t)s4.x * HD + cbase];
            uint4 g1 = *(const uint4*)&xl[(size_t)s4.y * HD + cbase];
            uint4 g2 = *(const uint4*)&xl[(size_t)s4.z * HD + cbase];
            uint4 g3 = *(const uint4*)&xl[(size_t)s4.w * HD + cbase];

            float4 a0A, a0B, a1A, a1B, a2A, a2B, a3A, a3B;
#define UNP(lo4, hi4, g) { \
    float2 p0 = __half22float2(*(__half2*)&g.x); \
    float2 p1 = __half22float2(*(__half2*)&g.y); \
    float2 p2 = __half22float2(*(__half2*)&g.z); \
    float2 p3 = __half22float2(*(__half2*)&g.w); \
    lo4 = make_float4(p0.x, p0.y, p1.x, p1.y); \
    hi4 = make_float4(p2.x, p2.y, p3.x, p3.y); }
            UNP(a0A, a0B, g0) UNP(a1A, a1B, g1) UNP(a2A, a2B, g2) UNP(a3A, a3B, g3)
#undef UNP

            float sc0, sc1, sc2, sc3;
#define SC(sc, lo, hi) { \
    float v0 = lo.x + xv0.x, v1 = lo.y + xv0.y; \
    float v2 = lo.z + xv0.z, v3 = lo.w + xv0.w; \
    float u0 = hi.x + xv1.x, u1 = hi.y + xv1.y; \
    float u2 = hi.z + xv1.z, u3 = hi.w + xv1.w; \
    v0 = v0 > 0.f ? v0 : 0.2f * v0; \
    v1 = v1 > 0.f ? v1 : 0.2f * v1; \
    v2 = v2 > 0.f ? v2 : 0.2f * v2; \
    v3 = v3 > 0.f ? v3 : 0.2f * v3; \
    u0 = u0 > 0.f ? u0 : 0.2f * u0; \
    u1 = u1 > 0.f ? u1 : 0.2f * u1; \
    u2 = u2 > 0.f ? u2 : 0.2f * u2; \
    u3 = u3 > 0.f ? u3 : 0.2f * u3; \
    float pA = v0 * a40.x; \
    float pB = v1 * a40.y; \
    pA = fmaf(v2, a40.z, pA); \
    pB = fmaf(v3, a40.w, pB); \
    pA = fmaf(u0, a41.x, pA); \
    pB = fmaf(u1, a41.y, pB); \
    pA = fmaf(u2, a41.z, pA); \
    pB = fmaf(u3, a41.w, pB); \
    sc = pA + pB; }
            SC(sc0, a0A, a0B) SC(sc1, a1A, a1B) SC(sc2, a2A, a2B) SC(sc3, a3A, a3B)
#undef SC

            // strides 2,1 (per-score partial over lane's group-of-4)
#pragma unroll
            for (int d = 2; d >= 1; d >>= 1) {
                sc0 += __shfl_xor_sync(F, sc0, d);
                sc1 += __shfl_xor_sync(F, sc1, d);
                sc2 += __shfl_xor_sync(F, sc2, d);
                sc3 += __shfl_xor_sync(F, sc3, d);
            }
            // select own residue; combine the 2 groups of this 8-lane head
            float v = (r4 < 2) ? (r4 ? sc1 : sc0) : ((r4 == 2) ? sc2 : sc3);
            v += __shfl_xor_sync(F, v, 4);

            int idx = j + r4;
            float ev = (idx >= beg && idx < end) ? __expf(v) : 0.f;
            den += ev;

            float e0 = __shfl_sync(F, ev, gbase);
            float e1 = __shfl_sync(F, ev, gbase | 1);
            float e2 = __shfl_sync(F, ev, gbase | 2);
            float e3 = __shfl_sync(F, ev, gbase | 3);

            ns0.x = fmaf(e0, a0A.x, ns0.x); ns0.y = fmaf(e0, a0A.y, ns0.y);
            ns0.z = fmaf(e0, a0A.z, ns0.z); ns0.w = fmaf(e0, a0A.w, ns0.w);
            ns1.x = fmaf(e0, a0B.x, ns1.x); ns1.y = fmaf(e0, a0B.y, ns1.y);
            ns1.z = fmaf(e0, a0B.z, ns1.z); ns1.w = fmaf(e0, a0B.w, ns1.w);
            ns0.x = fmaf(e1, a1A.x, ns0.x); ns0.y = fmaf(e1, a1A.y, ns0.y);
            ns0.z = fmaf(e1, a1A.z, ns0.z); ns0.w = fmaf(e1, a1A.w, ns0.w);
            ns1.x = fmaf(e1, a1B.x, ns1.x); ns1.y = fmaf(e1, a1B.y, ns1.y);
            ns1.z = fmaf(e1, a1B.z, ns1.z); ns1.w = fmaf(e1, a1B.w, ns1.w);
            ns0.x = fmaf(e2, a2A.x, ns0.x); ns0.y = fmaf(e2, a2A.y, ns0.y);
            ns0.z = fmaf(e2, a2A.z, ns0.z); ns0.w = fmaf(e2, a2A.w, ns0.w);
            ns1.x = fmaf(e2, a2B.x, ns1.x); ns1.y = fmaf(e2, a2B.y, ns1.y);
            ns1.z = fmaf(e2, a2B.z, ns1.z); ns1.w = fmaf(e2, a2B.w, ns1.w);
            ns0.x = fmaf(e3, a3A.x, ns0.x); ns0.y = fmaf(e3, a3A.y, ns0.y);
            ns0.z = fmaf(e3, a3A.z, ns0.z); ns0.w = fmaf(e3, a3A.w, ns0.w);
            ns1.x = fmaf(e3, a3B.x, ns1.x); ns1.y = fmaf(e3, a3B.y, ns1.y);
            ns1.z = fmaf(e3, a3B.z, ns1.z); ns1.w = fmaf(e3, a3B.w, ns1.w);
        }

        // den: combine residue partials within the group-of-4
        den += __shfl_xor_sync(F, den, 2);
        den += __shfl_xor_sync(F, den, 1);

        float inv = 0.25f / (den + 1e-16f);
        float4 s0, s1;
        s0.x = ns0.x * inv; s0.y = ns0.y * inv;
        s0.z = ns0.z * inv; s0.w = ns0.w * inv;
        s1.x = ns1.x * inv; s1.y = ns1.y * inv;
        s1.z = ns1.z * inv; s1.w = ns1.w * inv;

        // head fold: lane hl (<8, head0 dims 8hl..) += lane hl+8 (head1 same dims)
        s0.x += __shfl_xor_sync(F, s0.x, 8);
        s0.y += __shfl_xor_sync(F, s0.y, 8);
        s0.z += __shfl_xor_sync(F, s0.z, 8);
        s0.w += __shfl_xor_sync(F, s0.w, 8);
        s1.x += __shfl_xor_sync(F, s1.x, 8);
        s1.y += __shfl_xor_sync(F, s1.y, 8);
        s1.z += __shfl_xor_sync(F, s1.z, 8);
        s1.w += __shfl_xor_sync(F, s1.w, 8);

        out0.x += s0.x; out0.y += s0.y; out0.z += s0.z; out0.w += s0.w;
        out1.x += s1.x; out1.y += s1.y; out1.z += s1.z; out1.w += s1.w;
    }

    if (active && hl < 8) {
        int c = hl * 8;
        out0.x += 0.5f * (bias[c + 0] + bias[64 + c + 0]);
        out0.y += 0.5f * (bias[c + 1] + bias[64 + c + 1]);
        out0.z += 0.5f * (bias[c + 2] + bias[64 + c + 2]);
        out0.w += 0.5f * (bias[c + 3] + bias[64 + c + 3]);
        out1.x += 0.5f * (bias[c + 4] + bias[64 + c + 4]);
        out1.y += 0.5f * (bias[c + 5] + bias[64 + c + 5]);
        out1.z += 0.5f * (bias[c + 6] + bias[64 + c + 6]);
        out1.w += 0.5f * (bias[c + 7] + bias[64 + c + 7]);
        *(float4*)&out[(size_t)node * 64 + c]     = out0;
        *(float4*)&out[(size_t)node * 64 + c + 4] = out1;
    }
}

// ---------------------------------------------------------------------------
extern "C" void kernel_launch(void* const* d_in, const int* in_sizes, int n_in,
                              void* d_out, int out_size) {
    const float* x       = (const float*)d_in[0];
    const int*   e_adj   = (const int*)  d_in[1];
    const int*   e_ray   = (const int*)  d_in[2];
    const float* l1_Wl   = (const float*)d_in[3];
    const float* l1_bl   = (const float*)d_in[4];
    const float* l1_Wr   = (const float*)d_in[5];
    const float* l1_br   = (const float*)d_in[6];
    const float* l1_att  = (const float*)d_in[7];
    const float* l1_bias = (const float*)d_in[8];
    const float* l2_Wl   = (const float*)d_in[9];
    const float* l2_bl   = (const float*)d_in[10];
    const float* l2_Wr   = (const float*)d_in[11];
    const float* l2_br   = (const float*)d_in[12];
    const float* l2_att  = (const float*)d_in[13];
    const float* l2_bias = (const float*)d_in[14];

    const int N = in_sizes[0] / 2;
    const int E = in_sizes[1] / 2;

    __half* xlh; float *xrf, *h;
    int *rowptr, *cursor, *csrc;
    cudaGetSymbolAddress((void**)&xlh,    g_xlh);
    cudaGetSymbolAddress((void**)&xrf,    g_xr);
    cudaGetSymbolAddress((void**)&h,      g_h);
    cudaGetSymbolAddress((void**)&rowptr, g_rowptr);
    cudaGetSymbolAddress((void**)&cursor, g_cursor);
    cudaGetSymbolAddress((void**)&csrc,   g_csrc);

    const int ZB = 256;
    const int EB = (E + ZB - 1) / ZB;
    const int PULL_BLOCKS  = (N + 3) / 4;   // layer1: 1 node/warp
    const int PULL2_BLOCKS = (N + 7) / 8;   // layer2: 2 nodes/warp

    // ----- CSR build -----
    {
        dim3 g(EB, 2);
        hist2_kernel<<<g, ZB>>>(e_adj + E, e_ray + E, cursor, E);
    }
    scan2_kernel<<<2, 1024>>>(cursor, rowptr, N);
    {
        dim3 g(EB, 2);
        scatter2_kernel<<<g, ZB>>>(e_adj, e_ray, cursor, csrc, E);
    }

    // ----- Layer 1 (ncu capture slot #4) -----
    layer1_fused_kernel<<<PULL_BLOCKS, 128>>>(
        rowptr, csrc, x, l1_Wl, l1_bl, l1_Wr, l1_br, l1_att, l1_bias, h, N);

    // ----- Layer 2 -----
    {
        dim3 g((N + 31) / 32, 4);
        transform64_all_kernel<<<g, 128>>>(h, l2_Wl, l2_bl, l2_Wr, l2_br,
                                           xlh, xrf, N);
    }
    layer2_fused_kernel<<<PULL2_BLOCKS, 128>>>(
        rowptr, csrc, xlh, xrf, l2_att, l2_bias, (float*)d_out, N);

    // ----- Tail: re-zero cursors for the next call -----
    zero2_kernel<<<(N + ZB - 1) / ZB, ZB>>>(cursor, N);
}

// round 17
// speedup vs baseline: 1.2096x; 1.2096x over previous
#include <cuda_runtime.h>
#include <cuda_fp16.h>

// ============================================================================
// RFEncoder: 2-layer hetero GATv2 (2 relations, 2 heads, HID=64)
//
// R16: pulls reverted to R13 exactly (local optimum after 3 failed
// restructures). ONE change: transform64 uses 64-node tiles with 8 nodes per
// thread -> W smem fragments reused 8x (W-LDS phases per node halved; xv
// loads are cheap broadcasts). FFMA2 inner math kept.
// ============================================================================

#define NMAX  100000
#define EMAX  800000
#define EMAXP (EMAX + 4)
#define HD    128   // HEADS * HID

typedef unsigned long long u64;

__device__ __half g_xlh[2][NMAX * HD];
__device__ float  g_xr [2][NMAX * HD];
__device__ float  g_h  [NMAX * 64];
__device__ int    g_rowptr[2][NMAX + 1];
__device__ int    g_cursor[2][NMAX];
__device__ int    g_csrc  [2][EMAXP];

union F4U2 { float4 f; u64 u[2]; };

__device__ __forceinline__ u64 pack2(float lo, float hi) {
    u64 r; asm("mov.b64 %0, {%1, %2};" : "=l"(r) : "f"(lo), "f"(hi)); return r;
}
__device__ __forceinline__ u64 ffma2(u64 a, u64 b, u64 c) {
    u64 d; asm("fma.rn.f32x2 %0, %1, %2, %3;" : "=l"(d) : "l"(a), "l"(b), "l"(c));
    return d;
}

// ---------------------------------------------------------------------------
__global__ void zero2_kernel(int* __restrict__ cur, int n) {
    int i = blockIdx.x * blockDim.x + threadIdx.x;
    if (i < n) { cur[i] = 0; cur[NMAX + i] = 0; }
}

__global__ void hist2_kernel(const int* __restrict__ dst0,
                             const int* __restrict__ dst1,
                             int* __restrict__ cur, int E) {
    int e = blockIdx.x * blockDim.x + threadIdx.x;
    if (e >= E) return;
    const int* d = blockIdx.y ? dst1 : dst0;
    atomicAdd(&cur[blockIdx.y * NMAX + d[e]], 1);
}

__global__ void scan2_kernel(int* __restrict__ cursor, int* __restrict__ rowptr,
                             int n) {
    __shared__ int part[1024];
    int r = blockIdx.x;
    int* cur = cursor + r * NMAX;
    int* rp  = rowptr + r * (NMAX + 1);
    int t = threadIdx.x;
    int chunk = (n + 1023) / 1024;
    int lo = t * chunk;
    int hi = lo + chunk; if (hi > n) hi = n;

    int s = 0;
    for (int i = lo; i < hi; i++) s += cur[i];
    part[t] = s;
    __syncthreads();
    for (int d = 1; d < 1024; d <<= 1) {
        int v = (t >= d) ? part[t - d] : 0;
        __syncthreads();
        part[t] += v;
        __syncthreads();
    }
    int off = (t == 0) ? 0 : part[t - 1];
    for (int i = lo; i < hi; i++) {
        int dv = cur[i];
        rp[i] = off;
        cur[i] = off;
        off += dv;
    }
    if (hi == n) rp[n] = off;
}

__global__ void scatter2_kernel(const int* __restrict__ ea,
                                const int* __restrict__ er,
                                int* __restrict__ cursor,
                                int* __restrict__ csrc, int E) {
    int e = blockIdx.x * blockDim.x + threadIdx.x;
    if (e >= E) return;
    int r = blockIdx.y;
    const int* edges = r ? er : ea;
    int pos = atomicAdd(&cursor[r * NMAX + edges[E + e]], 1);
    csrc[r * EMAXP + pos] = edges[e];
}

// ---------------------------------------------------------------------------
// Layer 1, fully fused (R13 version, unchanged).
__global__ void __launch_bounds__(128, 8)
layer1_fused_kernel(const int* __restrict__ rowptr,
                    const int* __restrict__ csrc,
                    const float* __restrict__ x,
                    const float* __restrict__ Wl,
                    const float* __restrict__ bl,
                    const float* __restrict__ Wr,
                    const float* __restrict__ br,
                    const float* __restrict__ att,
                    const float* __restrict__ bias,
                    float* __restrict__ h, int n) {
    const unsigned F = 0xffffffffu;
    int node = (blockIdx.x * blockDim.x + threadIdx.x) >> 5;
    if (node >= n) return;
    int lane = threadIdx.x & 31;
    int r4   = lane & 3;

    const float2 xd = ((const float2*)x)[node];
    float4 outv = make_float4(0.f, 0.f, 0.f, 0.f);

#pragma unroll 1
    for (int r = 0; r < 2; r++) {
        const float4 wl0 = *(const float4*)&Wl[r * 256 + lane * 4];
        const float4 wl1 = *(const float4*)&Wl[r * 256 + HD + lane * 4];
        const float4 blv = *(const float4*)&bl[r * HD + lane * 4];
        const float4 a4  = *(const float4*)&att[r * HD + lane * 4];

        float4 base;
        {
            const float4 wr0 = *(const float4*)&Wr[r * 256 + lane * 4];
            const float4 wr1 = *(const float4*)&Wr[r * 256 + HD + lane * 4];
            const float4 brv = *(const float4*)&br[r * HD + lane * 4];
            base.x = fmaf(xd.y, wr1.x, fmaf(xd.x, wr0.x, brv.x)) + blv.x;
            base.y = fmaf(xd.y, wr1.y, fmaf(xd.x, wr0.y, brv.y)) + blv.y;
            base.z = fmaf(xd.y, wr1.z, fmaf(xd.x, wr0.z, brv.z)) + blv.z;
            base.w = fmaf(xd.y, wr1.w, fmaf(xd.x, wr0.w, brv.w)) + blv.w;
        }

        const int* rp = rowptr + r * (NMAX + 1);
        const int* cs = csrc   + r * EMAXP;
        int beg = rp[node];
        int end = rp[node + 1];

        float S0 = 0.f, S1 = 0.f, den = 0.f;

        for (int j = beg & ~3; j < end; j += 4) {
            int4 s4 = *(const int4*)&cs[j];

            float2 q0 = ((const float2*)x)[s4.x];
            float2 q1 = ((const float2*)x)[s4.y];
            float2 q2 = ((const float2*)x)[s4.z];
            float2 q3 = ((const float2*)x)[s4.w];

            float sc0, sc1, sc2, sc3;
#define SCORE1(sc, q) { \
    float v0 = fmaf(q.y, wl1.x, fmaf(q.x, wl0.x, base.x)); \
    float v1 = fmaf(q.y, wl1.y, fmaf(q.x, wl0.y, base.y)); \
    float v2 = fmaf(q.y, wl1.z, fmaf(q.x, wl0.z, base.z)); \
    float v3 = fmaf(q.y, wl1.w, fmaf(q.x, wl0.w, base.w)); \
    v0 = v0 > 0.f ? v0 : 0.2f * v0; \
    v1 = v1 > 0.f ? v1 : 0.2f * v1; \
    v2 = v2 > 0.f ? v2 : 0.2f * v2; \
    v3 = v3 > 0.f ? v3 : 0.2f * v3; \
    float pA = v0 * a4.x; \
    float pB = v1 * a4.y; \
    pA = fmaf(v2, a4.z, pA); \
    pB = fmaf(v3, a4.w, pB); \
    sc = pA + pB; }
            SCORE1(sc0, q0) SCORE1(sc1, q1) SCORE1(sc2, q2) SCORE1(sc3, q3)
#undef SCORE1

#pragma unroll
            for (int d = 2; d >= 1; d >>= 1) {
                sc0 += __shfl_xor_sync(F, sc0, d);
                sc1 += __shfl_xor_sync(F, sc1, d);
                sc2 += __shfl_xor_sync(F, sc2, d);
                sc3 += __shfl_xor_sync(F, sc3, d);
            }
            float v = (r4 < 2) ? (r4 ? sc1 : sc0) : ((r4 == 2) ? sc2 : sc3);
            v += __shfl_xor_sync(F, v, 4);
            v += __shfl_xor_sync(F, v, 8);

            int idx = j + r4;
            float ev = (idx >= beg && idx < end) ? __expf(v) : 0.f;

            float qx = (r4 < 2) ? (r4 ? q1.x : q0.x) : ((r4 == 2) ? q2.x : q3.x);
            float qy = (r4 < 2) ? (r4 ? q1.y : q0.y) : ((r4 == 2) ? q2.y : q3.y);
            S0 = fmaf(ev, qx, S0);
            S1 = fmaf(ev, qy, S1);
            den += ev;
        }

        S0  += __shfl_xor_sync(F, S0, 2);  S0  += __shfl_xor_sync(F, S0, 1);
        S1  += __shfl_xor_sync(F, S1, 2);  S1  += __shfl_xor_sync(F, S1, 1);
        den += __shfl_xor_sync(F, den, 2); den += __shfl_xor_sync(F, den, 1);

        float inv = 0.25f / (den + 1e-16f);
        outv.x = fmaf(fmaf(S1, wl1.x, fmaf(S0, wl0.x, den * blv.x)), inv, outv.x);
        outv.y = fmaf(fmaf(S1, wl1.y, fmaf(S0, wl0.y, den * blv.y)), inv, outv.y);
        outv.z = fmaf(fmaf(S1, wl1.z, fmaf(S0, wl0.z, den * blv.z)), inv, outv.z);
        outv.w = fmaf(fmaf(S1, wl1.w, fmaf(S0, wl0.w, den * blv.w)), inv, outv.w);
    }

    outv.x += __shfl_xor_sync(F, outv.x, 16);
    outv.y += __shfl_xor_sync(F, outv.y, 16);
    outv.z += __shfl_xor_sync(F, outv.z, 16);
    outv.w += __shfl_xor_sync(F, outv.w, 16);

    if (lane < 16) {
        int c = lane * 4;
        outv.x += 0.5f * (bias[c + 0] + bias[64 + c + 0]);
        outv.y += 0.5f * (bias[c + 1] + bias[64 + c + 1]);
        outv.z += 0.5f * (bias[c + 2] + bias[64 + c + 2]);
        outv.w += 0.5f * (bias[c + 3] + bias[64 + c + 3]);
        outv.x = outv.x > 0.f ? outv.x : 0.f;
        outv.y = outv.y > 0.f ? outv.y : 0.f;
        outv.z = outv.z > 0.f ? outv.z : 0.f;
        outv.w = outv.w > 0.f ? outv.w : 0.f;
        *(float4*)&h[(size_t)node * 64 + c] = outv;
    }
}

// ---------------------------------------------------------------------------
// Layer-2 transforms: 64-node tiles, 8 nodes per thread (W reuse x8), FFMA2.
__global__ void __launch_bounds__(128)
transform64_all_kernel(const float* __restrict__ X,
                       const float* __restrict__ Wl,
                       const float* __restrict__ bl,
                       const float* __restrict__ Wr,
                       const float* __restrict__ br,
                       __half* __restrict__ xlh,
                       float* __restrict__ xrf,
                       int n) {
    __shared__ float sW[64 * 128];   // 32 KB
    __shared__ float sX[64 * 68];    // 17.4 KB

    int y = blockIdx.y;
    int r = y >> 1;
    bool is_xl = (y & 1) == 0;
    const float* W = is_xl ? (Wl + r * 64 * HD) : (Wr + r * 64 * HD);
    const float* b = is_xl ? (bl + r * HD)      : (br + r * HD);

    int tx = threadIdx.x;
    for (int idx = tx * 4; idx < 64 * 128; idx += 128 * 4)
        *(float4*)&sW[idx] = *(const float4*)&W[idx];

    int node0 = blockIdx.x * 64;
    for (int idx = tx; idx < 1024; idx += 128) {
        int rr = idx >> 4;
        int c4 = idx & 15;
        float4 v = make_float4(0.f, 0.f, 0.f, 0.f);
        if (node0 + rr < n)
            v = *(const float4*)&X[(size_t)(node0 + rr) * 64 + c4 * 4];
        *(float4*)&sX[rr * 68 + c4 * 4] = v;
    }
    __syncthreads();

    int cg = tx & 15;    // 16 col groups x 8 cols
    int ng = tx >> 4;    // 8 node groups x 8 nodes

    u64 acc2[8][4];
    {
        u64 b0 = pack2(b[cg * 8 + 0], b[cg * 8 + 1]);
        u64 b1 = pack2(b[cg * 8 + 2], b[cg * 8 + 3]);
        u64 b2 = pack2(b[cg * 8 + 4], b[cg * 8 + 5]);
        u64 b3 = pack2(b[cg * 8 + 6], b[cg * 8 + 7]);
#pragma unroll
        for (int m = 0; m < 8; m++) {
            acc2[m][0] = b0; acc2[m][1] = b1;
            acc2[m][2] = b2; acc2[m][3] = b3;
        }
    }

    for (int k = 0; k < 64; k += 4) {
        float4 xv[8];
#pragma unroll
        for (int m = 0; m < 8; m++)
            xv[m] = *(const float4*)&sX[(ng * 8 + m) * 68 + k];
#pragma unroll
        for (int kk = 0; kk < 4; kk++) {
            F4U2 w0, w1;
            w0.f = *(const float4*)&sW[(k + kk) * 128 + cg * 8];
            w1.f = *(const float4*)&sW[(k + kk) * 128 + cg * 8 + 4];
#pragma unroll
            for (int m = 0; m < 8; m++) {
                float xs = (kk == 0) ? xv[m].x : (kk == 1) ? xv[m].y
                         : (kk == 2) ? xv[m].z : xv[m].w;
                u64 xs2 = pack2(xs, xs);
                acc2[m][0] = ffma2(xs2, w0.u[0], acc2[m][0]);
                acc2[m][1] = ffma2(xs2, w0.u[1], acc2[m][1]);
                acc2[m][2] = ffma2(xs2, w1.u[0], acc2[m][2]);
                acc2[m][3] = ffma2(xs2, w1.u[1], acc2[m][3]);
            }
        }
    }

    if (is_xl) {
        __half* Y = xlh + (size_t)r * NMAX * HD;
#pragma unroll
        for (int m = 0; m < 8; m++) {
            int node = node0 + ng * 8 + m;
            if (node < n) {
                F4U2 o0, o1;
                o0.u[0] = acc2[m][0]; o0.u[1] = acc2[m][1];
                o1.u[0] = acc2[m][2]; o1.u[1] = acc2[m][3];
                __half2 p0 = __float22half2_rn(make_float2(o0.f.x, o0.f.y));
                __half2 p1 = __float22half2_rn(make_float2(o0.f.z, o0.f.w));
                __half2 p2 = __float22half2_rn(make_float2(o1.f.x, o1.f.y));
                __half2 p3 = __float22half2_rn(make_float2(o1.f.z, o1.f.w));
                uint4 pk;
                pk.x = *(unsigned*)&p0; pk.y = *(unsigned*)&p1;
                pk.z = *(unsigned*)&p2; pk.w = *(unsigned*)&p3;
                *(uint4*)&Y[(size_t)node * HD + cg * 8] = pk;
            }
        }
    } else {
        float* Y = xrf + (size_t)r * NMAX * HD;
#pragma unroll
        for (int m = 0; m < 8; m++) {
            int node = node0 + ng * 8 + m;
            if (node < n) {
                F4U2 o0, o1;
                o0.u[0] = acc2[m][0]; o0.u[1] = acc2[m][1];
                o1.u[0] = acc2[m][2]; o1.u[1] = acc2[m][3];
                *(float4*)&Y[(size_t)node * HD + cg * 8]     = o0.f;
                *(float4*)&Y[(size_t)node * HD + cg * 8 + 4] = o1.f;
            }
        }
    }
}

// ---------------------------------------------------------------------------
// Layer-2 fused pull (R13/R9 version, unchanged).
__global__ void __launch_bounds__(128, 8)
layer2_fused_kernel(const int* __restrict__ rowptr,
                    const int* __restrict__ csrc,
                    const __half* __restrict__ xlh,
                    const float* __restrict__ xrf,
                    const float* __restrict__ att,
                    const float* __restrict__ bias,
                    float* __restrict__ out, int n) {
    const unsigned F = 0xffffffffu;
    int node = (blockIdx.x * blockDim.x + threadIdx.x) >> 5;
    if (node >= n) return;
    int lane = threadIdx.x & 31;

    float4 outv = make_float4(0.f, 0.f, 0.f, 0.f);

#pragma unroll 1
    for (int r = 0; r < 2; r++) {
        const __half* xl = xlh + (size_t)r * NMAX * HD;
        const float*  xr = xrf + (size_t)r * NMAX * HD;
        const float4 a4  = *(const float4*)&att[r * HD + lane * 4];
        const float4 xrv = *(const float4*)&xr[(size_t)node * HD + lane * 4];

        const int* rp = rowptr + r * (NMAX + 1);
        const int* cs = csrc   + r * EMAXP;
        int beg = rp[node];
        int end = rp[node + 1];

        float4 ns = make_float4(0.f, 0.f, 0.f, 0.f);
        float den = 0.f;

        for (int bse = beg; bse < end; bse += 32) {
            int cnt = end - bse; if (cnt > 32) cnt = 32;
            int ld = bse + lane; if (ld >= end) ld = end - 1;
            int sv = cs[ld];

            for (int j = 0; j < cnt; j += 4) {
                int i1 = (j + 1 < cnt) ? j + 1 : j;
                int i2 = (j + 2 < cnt) ? j + 2 : j;
                int i3 = (j + 3 < cnt) ? j + 3 : j;
                int s0 = __shfl_sync(F, sv, j);
                int s1 = __shfl_sync(F, sv, i1);
                int s2 = __shfl_sync(F, sv, i2);
                int s3 = __shfl_sync(F, sv, i3);

                uint2 r0 = *(const uint2*)&xl[(size_t)s0 * HD + lane * 4];
                uint2 r1 = *(const uint2*)&xl[(size_t)s1 * HD + lane * 4];
                uint2 r2 = *(const uint2*)&xl[(size_t)s2 * HD + lane * 4];
                uint2 r3 = *(const uint2*)&xl[(size_t)s3 * HD + lane * 4];

                float4 a0, a1, a2, a3;
#define UNPACK(a, rr) { \
    float2 lo = __half22float2(*(__half2*)&rr.x); \
    float2 hi = __half22float2(*(__half2*)&rr.y); \
    a = make_float4(lo.x, lo.y, hi.x, hi.y); }
                UNPACK(a0, r0) UNPACK(a1, r1) UNPACK(a2, r2) UNPACK(a3, r3)
#undef UNPACK

                float sc0, sc1, sc2, sc3;
#define SCORE(sc, a) { \
    float v0 = a.x + xrv.x; \
    float v1 = a.y + xrv.y; \
    float v2 = a.z + xrv.z; \
    float v3 = a.w + xrv.w; \
    v0 = v0 > 0.f ? v0 : 0.2f * v0; \
    v1 = v1 > 0.f ? v1 : 0.2f * v1; \
    v2 = v2 > 0.f ? v2 : 0.2f * v2; \
    v3 = v3 > 0.f ? v3 : 0.2f * v3; \
    float pA = v0 * a4.x; \
    float pB = v1 * a4.y; \
    pA = fmaf(v2, a4.z, pA); \
    pB = fmaf(v3, a4.w, pB); \
    sc = pA + pB; }
                SCORE(sc0, a0) SCORE(sc1, a1) SCORE(sc2, a2) SCORE(sc3, a3)
#undef SCORE

#pragma unroll
                for (int d = 8; d >= 1; d >>= 1) {
                    sc0 += __shfl_xor_sync(F, sc0, d);
                    sc1 += __shfl_xor_sync(F, sc1, d);
                    sc2 += __shfl_xor_sync(F, sc2, d);
                    sc3 += __shfl_xor_sync(F, sc3, d);
                }

                float e0 = __expf(sc0);
                float e1 = (j + 1 < cnt) ? __expf(sc1) : 0.f;
                float e2 = (j + 2 < cnt) ? __expf(sc2) : 0.f;
                float e3 = (j + 3 < cnt) ? __expf(sc3) : 0.f;

                ns.x = fmaf(e0, a0.x, ns.x); ns.y = fmaf(e0, a0.y, ns.y);
                ns.z = fmaf(e0, a0.z, ns.z); ns.w = fmaf(e0, a0.w, ns.w);
                ns.x = fmaf(e1, a1.x, ns.x); ns.y = fmaf(e1, a1.y, ns.y);
                ns.z = fmaf(e1, a1.z, ns.z); ns.w = fmaf(e1, a1.w, ns.w);
                ns.x = fmaf(e2, a2.x, ns.x); ns.y = fmaf(e2, a2.y, ns.y);
                ns.z = fmaf(e2, a2.z, ns.z); ns.w = fmaf(e2, a2.w, ns.w);
                ns.x = fmaf(e3, a3.x, ns.x); ns.y = fmaf(e3, a3.y, ns.y);
                ns.z = fmaf(e3, a3.z, ns.z); ns.w = fmaf(e3, a3.w, ns.w);
                den += e0 + e1 + e2 + e3;
            }
        }

        float inv = 0.25f / (den + 1e-16f);
        outv.x = fmaf(ns.x, inv, outv.x);
        outv.y = fmaf(ns.y, inv, outv.y);
        outv.z = fmaf(ns.z, inv, outv.z);
        outv.w = fmaf(ns.w, inv, outv.w);
    }

    outv.x += __shfl_xor_sync(F, outv.x, 16);
    outv.y += __shfl_xor_sync(F, outv.y, 16);
    outv.z += __shfl_xor_sync(F, outv.z, 16);
    outv.w += __shfl_xor_sync(F, outv.w, 16);

    if (lane < 16) {
        int c = lane * 4;
        outv.x += 0.5f * (bias[c + 0] + bias[64 + c + 0]);
        outv.y += 0.5f * (bias[c + 1] + bias[64 + c + 1]);
        outv.z += 0.5f * (bias[c + 2] + bias[64 + c + 2]);
        outv.w += 0.5f * (bias[c + 3] + bias[64 + c + 3]);
        *(float4*)&out[(size_t)node * 64 + c] = outv;
    }
}

// ---------------------------------------------------------------------------
extern "C" void kernel_launch(void* const* d_in, const int* in_sizes, int n_in,
                              void* d_out, int out_size) {
    const float* x       = (const float*)d_in[0];
    const int*   e_adj   = (const int*)  d_in[1];
    const int*   e_ray   = (const int*)  d_in[2];
    const float* l1_Wl   = (const float*)d_in[3];
    const float* l1_bl   = (const float*)d_in[4];
    const float* l1_Wr   = (const float*)d_in[5];
    const float* l1_br   = (const float*)d_in[6];
    const float* l1_att  = (const float*)d_in[7];
    const float* l1_bias = (const float*)d_in[8];
    const float* l2_Wl   = (const float*)d_in[9];
    const float* l2_bl   = (const float*)d_in[10];
    const float* l2_Wr   = (const float*)d_in[11];
    const float* l2_br   = (const float*)d_in[12];
    const float* l2_att  = (const float*)d_in[13];
    const float* l2_bias = (const float*)d_in[14];

    const int N = in_sizes[0] / 2;
    const int E = in_sizes[1] / 2;

    __half* xlh; float *xrf, *h;
    int *rowptr, *cursor, *csrc;
    cudaGetSymbolAddress((void**)&xlh,    g_xlh);
    cudaGetSymbolAddress((void**)&xrf,    g_xr);
    cudaGetSymbolAddress((void**)&h,      g_h);
    cudaGetSymbolAddress((void**)&rowptr, g_rowptr);
    cudaGetSymbolAddress((void**)&cursor, g_cursor);
    cudaGetSymbolAddress((void**)&csrc,   g_csrc);

    const int ZB = 256;
    const int EB = (E + ZB - 1) / ZB;
    const int PULL_BLOCKS = (N + 3) / 4;

    // ----- CSR build -----
    {
        dim3 g(EB, 2);
        hist2_kernel<<<g, ZB>>>(e_adj + E, e_ray + E, cursor, E);
    }
    scan2_kernel<<<2, 1024>>>(cursor, rowptr, N);
    {
        dim3 g(EB, 2);
        scatter2_kernel<<<g, ZB>>>(e_adj, e_ray, cursor, csrc, E);
    }

    // ----- Layer 1 (ncu capture slot #4) -----
    layer1_fused_kernel<<<PULL_BLOCKS, 128>>>(
        rowptr, csrc, x, l1_Wl, l1_bl, l1_Wr, l1_br, l1_att, l1_bias, h, N);

    // ----- Layer 2 -----
    {
        dim3 g((N + 63) / 64, 4);
        transform64_all_kernel<<<g, 128>>>(h, l2_Wl, l2_bl, l2_Wr, l2_br,
                                           xlh, xrf, N);
    }
    layer2_fused_kernel<<<PULL_BLOCKS, 128>>>(
        rowptr, csrc, xlh, xrf, l2_att, l2_bias, (float*)d_out, N);

    // ----- Tail: re-zero cursors for the next call -----
    zero2_kernel<<<(N + ZB - 1) / ZB, ZB>>>(cursor, N);
}